// round 16
// baseline (speedup 1.0000x reference)
#include <cuda_runtime.h>
#include <cuda_bf16.h>

#define Nn  8
#define Cc  64
#define Hh  128
#define Ww  512
#define CoN 64
#define HW  (Hh * Ww)      // 65536
#define NOFF 18
#define CSTR 36            // deform chunk tile stride (floats): 144B, conflict-free
#define XSTR 136           // offset-conv x-tile stride

// Scratch: offsets, channel-quad-packed x, tf32 B-fragment tables.
__device__ float  g_off[(size_t)Nn * NOFF * HW];   // ~36 MB
__device__ float4 g_x4[(size_t)Nn * 16 * HW];      // ~134 MB  [n][c/4][y][x]
__device__ float2 g_wfrag[9 * 8 * 8 * 32];         // deform B frags [t][k][ni][lane]
__device__ float2 g_wofrag[72 * 3 * 32];           // offset B frags

__device__ __forceinline__ unsigned f2tf32(float v) {
    unsigned u;
    asm("cvt.rna.tf32.f32 %0, %1;" : "=r"(u) : "f"(v));
    return u;
}

// ---------------------------------------------------------------------------
// Kernel T: pack x NCHW -> [n][c/4][y][x] float4 (channel-quad interleave).
// ---------------------------------------------------------------------------
__global__ void __launch_bounds__(256) pack4_kernel(const float* __restrict__ x) {
    int idx = blockIdx.x * 256 + threadIdx.x;   // over Nn*16*HW
    int yx   = idx & (HW - 1);
    int rest = idx >> 16;
    int cq   = rest & 15;
    int n    = rest >> 4;
    const float* src = x + ((size_t)(n * 64 + cq * 4)) * HW + yx;
    g_x4[idx] = make_float4(src[0], src[HW], src[2 * HW], src[3 * HW]);
}

// ---------------------------------------------------------------------------
// Kernel 0a: deform B fragments (m16n8k8 tf32).
// ---------------------------------------------------------------------------
__global__ void wfrag_kernel(const float* __restrict__ wdef) {
    int idx = blockIdx.x * 256 + threadIdx.x;
    if (idx >= 9 * 8 * 8 * 32) return;
    int lane = idx & 31;
    int ni   = (idx >> 5) & 7;
    int k    = (idx >> 8) & 7;
    int t    = idx >> 11;
    int c = 8 * k + (lane & 3);
    int o = 8 * ni + (lane >> 2);
    float b0 = wdef[(o * 64 + c) * 9 + t];
    float b1 = wdef[(o * 64 + c + 4) * 9 + t];
    g_wfrag[idx] = make_float2(__uint_as_float(f2tf32(b0)),
                               __uint_as_float(f2tf32(b1)));
}

// ---------------------------------------------------------------------------
// Kernel 0b: offset-conv B fragments (oc padded 18 -> 24).
// ---------------------------------------------------------------------------
__global__ void wofrag_kernel(const float* __restrict__ woff) {
    int idx = blockIdx.x * 256 + threadIdx.x;
    if (idx >= 72 * 3 * 32) return;
    int lane = idx & 31;
    int rem  = idx >> 5;
    int ni   = rem % 3;
    int ks   = rem / 3;
    int gr = lane >> 2, tc = lane & 3;
    int k0 = 8 * ks + tc;
    int oc = 8 * ni + gr;
    float b0 = (oc < 18) ? woff[oc * 576 + k0]     : 0.0f;
    float b1 = (oc < 18) ? woff[oc * 576 + k0 + 4] : 0.0f;
    g_wofrag[(ks * 3 + ni) * 32 + lane] =
        make_float2(__uint_as_float(f2tf32(b0)), __uint_as_float(f2tf32(b1)));
}

// ---------------------------------------------------------------------------
// Kernel 1: offset conv via tf32 MMA, row-pair + quad fill (Round 15 verbatim).
// ---------------------------------------------------------------------------
__global__ void __launch_bounds__(128) offset_mma_kernel(
    const float* __restrict__ boff)
{
    __shared__ float sx[32 * XSTR];   // 17408 B

    int tid  = threadIdx.x;
    int lane = tid & 31;
    int warp = tid >> 5;
    int gr   = lane >> 2;
    int tc   = lane & 3;
    int rowsel = warp >> 1;
    int pxb    = 64 * (warp & 1);

    int x0 = blockIdx.x * 128;
    int y0 = blockIdx.y * 2;
    int n  = blockIdx.z;

    float acc[4][3][4];
#pragma unroll
    for (int ni = 0; ni < 3; ni++) {
        int oc = 8 * ni + 2 * tc;
        float blo = (oc < 18)     ? __ldg(&boff[oc])     : 0.0f;
        float bhi = (oc + 1 < 18) ? __ldg(&boff[oc + 1]) : 0.0f;
#pragma unroll
        for (int mi = 0; mi < 4; mi++) {
            acc[mi][ni][0] = blo; acc[mi][ni][1] = bhi;
            acc[mi][ni][2] = blo; acc[mi][ni][3] = bhi;
        }
    }

    const float4* xq = g_x4 + (size_t)n * 16 * HW;

    for (int ch = 0; ch < 8; ch++) {
        __syncthreads();
        for (int idx = tid; idx < 1040; idx += 128) {
            int row8 = idx / 130;
            int col  = idx - 130 * row8;
            int qi   = row8 >> 2;
            int i    = row8 & 3;
            int yy = y0 + i - 1;
            int xx = x0 + col - 1;
            float4 v = make_float4(0.f, 0.f, 0.f, 0.f);
            if (yy >= 0 && yy < Hh && xx >= 0 && xx < Ww)
                v = xq[(size_t)(ch * 2 + qi) * HW + yy * Ww + xx];
            int rbase = ((qi << 2) << 2) + i;
            sx[(rbase)      * XSTR + col] = __uint_as_float(f2tf32(v.x));
            sx[(rbase + 4)  * XSTR + col] = __uint_as_float(f2tf32(v.y));
            sx[(rbase + 8)  * XSTR + col] = __uint_as_float(f2tf32(v.z));
            sx[(rbase + 12) * XSTR + col] = __uint_as_float(f2tf32(v.w));
        }
        __syncthreads();

#pragma unroll
        for (int kk = 0; kk < 9; kk++) {
            int kl = 8 * kk + tc;
            int c0 = kl / 9,  t0 = kl - 9 * c0;
            int i0 = t0 / 3,  j0 = t0 - 3 * i0;
            int kl2 = kl + 4;
            int c1 = kl2 / 9, t1 = kl2 - 9 * c1;
            int i1 = t1 / 3,  j1 = t1 - 3 * i1;
            int off0 = ((c0 << 2) + i0 + rowsel) * XSTR + j0 + pxb;
            int off1 = ((c1 << 2) + i1 + rowsel) * XSTR + j1 + pxb;

            const float2* wf = g_wofrag + (size_t)(ch * 9 + kk) * 96;
            float2 bfr[3];
#pragma unroll
            for (int ni = 0; ni < 3; ni++) bfr[ni] = __ldg(&wf[ni * 32 + lane]);

#pragma unroll
            for (int mi = 0; mi < 4; mi++) {
                int m = mi * 16 + gr;
                unsigned a0 = __float_as_uint(sx[off0 + m]);
                unsigned a1 = __float_as_uint(sx[off0 + m + 8]);
                unsigned a2 = __float_as_uint(sx[off1 + m]);
                unsigned a3 = __float_as_uint(sx[off1 + m + 8]);
#pragma unroll
                for (int ni = 0; ni < 3; ni++) {
                    unsigned b0 = __float_as_uint(bfr[ni].x);
                    unsigned b1 = __float_as_uint(bfr[ni].y);
                    asm volatile(
                        "mma.sync.aligned.m16n8k8.row.col.f32.tf32.tf32.f32 "
                        "{%0,%1,%2,%3}, {%4,%5,%6,%7}, {%8,%9}, {%0,%1,%2,%3};"
                        : "+f"(acc[mi][ni][0]), "+f"(acc[mi][ni][1]),
                          "+f"(acc[mi][ni][2]), "+f"(acc[mi][ni][3])
                        : "r"(a0), "r"(a1), "r"(a2), "r"(a3),
                          "r"(b0), "r"(b1));
                }
            }
        }
    }

    size_t ob = (size_t)n * NOFF * HW + (size_t)(y0 + rowsel) * Ww + x0 + pxb;
#pragma unroll
    for (int ni = 0; ni < 3; ni++) {
        int oc = 8 * ni + 2 * tc;
#pragma unroll
        for (int mi = 0; mi < 4; mi++) {
            int pr = mi * 16 + gr;
            if (oc < 18) {
                g_off[ob + (size_t)oc * HW + pr]     = acc[mi][ni][0];
                g_off[ob + (size_t)oc * HW + pr + 8] = acc[mi][ni][2];
            }
            if (oc + 1 < 18) {
                g_off[ob + (size_t)(oc + 1) * HW + pr]     = acc[mi][ni][1];
                g_off[ob + (size_t)(oc + 1) * HW + pr + 8] = acc[mi][ni][3];
            }
        }
    }
}

// ---------------------------------------------------------------------------
// Kernel 2: deformable conv — Round-14 structure, K CHUNKED 2x32 to halve the
// smem tile (2 x 9.2 KB double buffer) -> 12 CTAs/SM (occupancy 2x).
// Per tap: corners once; per chunk hc: warp (g,h) gathers 4 quads (16 ch) of
// its 32 pixels, pair barrier, 4 MMA k-steps (global k = 4*hc + kq; ascending
// k order preserved -> output bit-identical to Round 14).
// ---------------------------------------------------------------------------
__global__ void __launch_bounds__(128, 12) deform_mma_kernel(
    const float* __restrict__ bdef,
    float* __restrict__ out)
{
    __shared__ __align__(16) float sS[2][64 * CSTR];   // 2 x 9216 B

    int tid  = threadIdx.x;
    int lane = tid & 31;
    int warp = tid >> 5;
    int g    = warp & 1;      // pixel group
    int h    = warp >> 1;     // och quarter base / gather 16-ch half of chunk
    int gr   = lane >> 2;
    int tc   = lane & 3;

    int x0  = blockIdx.x * 64;
    int y   = blockIdx.y;
    int n   = blockIdx.z;
    int pxl = tid & 63;
    int xg  = x0 + pxl;

    float acc[2][4][4];
#pragma unroll
    for (int ni = 0; ni < 4; ni++) {
        int ni_g = 4 * h + ni;
        float blo = __ldg(&bdef[8 * ni_g + 2 * tc]);
        float bhi = __ldg(&bdef[8 * ni_g + 2 * tc + 1]);
#pragma unroll
        for (int mi = 0; mi < 2; mi++) {
            acc[mi][ni][0] = blo; acc[mi][ni][1] = bhi;
            acc[mi][ni][2] = blo; acc[mi][ni][3] = bhi;
        }
    }

    const float4* xqb = g_x4 + (size_t)n * 16 * HW;   // chunk/half added below
    const float* offb = g_off + (size_t)n * NOFF * HW + (size_t)y * Ww + xg;

    float dy = offb[0];
    float dx = offb[(size_t)HW];

    int bufsel = 0;

    for (int t = 0; t < 9; t++) {
        int i = t / 3, j = t % 3;
        float py  = (float)(y + i - 1) + dy;
        float pxf = (float)(xg + j - 1) + dx;

        if (t < 8) {
            dy = offb[(size_t)(2 * t + 2) * HW];
            dx = offb[(size_t)(2 * t + 3) * HW];
        }

        float fy = floorf(py), fx = floorf(pxf);
        float wy1 = py - fy, wx1 = pxf - fx;
        float wy0 = 1.0f - wy1, wx0 = 1.0f - wx1;
        int iy0 = (int)fy, ix0 = (int)fx;
        int iy1 = iy0 + 1, ix1 = ix0 + 1;

        float gy0 = (iy0 >= 0 && iy0 < Hh) ? wy0 : 0.0f;
        float gy1 = (iy1 >= 0 && iy1 < Hh) ? wy1 : 0.0f;
        float gx0 = (ix0 >= 0 && ix0 < Ww) ? wx0 : 0.0f;
        float gx1 = (ix1 >= 0 && ix1 < Ww) ? wx1 : 0.0f;
        float c00 = gy0 * gx0, c01 = gy0 * gx1;
        float c10 = gy1 * gx0, c11 = gy1 * gx1;

        int yc0 = min(max(iy0, 0), Hh - 1), yc1 = min(max(iy1, 0), Hh - 1);
        int xc0 = min(max(ix0, 0), Ww - 1), xc1 = min(max(ix1, 0), Ww - 1);
        int o00 = yc0 * Ww + xc0, o01 = yc0 * Ww + xc1;
        int o10 = yc1 * Ww + xc0, o11 = yc1 * Ww + xc1;

#pragma unroll
        for (int hc = 0; hc < 2; hc++) {
            float* buf = sS[bufsel];
            bufsel ^= 1;

            {   // gather 4 quads (16 ch) of chunk hc, half h, pixel pxl
                float4* srow = (float4*)(buf + pxl * CSTR + 16 * h);
                const float4* p = xqb + (size_t)(hc * 8 + h * 4) * HW;
#pragma unroll
                for (int q = 0; q < 4; q++) {
                    float4 a = p[o00];
                    float4 b = p[o01];
                    float4 c = p[o10];
                    float4 d = p[o11];
                    float4 v;
                    v.x = fmaf(c11, d.x, fmaf(c10, c.x, fmaf(c01, b.x, c00 * a.x)));
                    v.y = fmaf(c11, d.y, fmaf(c10, c.y, fmaf(c01, b.y, c00 * a.y)));
                    v.z = fmaf(c11, d.z, fmaf(c10, c.z, fmaf(c01, b.z, c00 * a.z)));
                    v.w = fmaf(c11, d.w, fmaf(c10, c.w, fmaf(c01, b.w, c00 * a.w)));
                    v.x = __uint_as_float(f2tf32(v.x));
                    v.y = __uint_as_float(f2tf32(v.y));
                    v.z = __uint_as_float(f2tf32(v.z));
                    v.w = __uint_as_float(f2tf32(v.w));
                    srow[q] = v;
                    p += HW;
                }
            }

            // pair barrier: both 16-ch halves of this chunk written for group g
            asm volatile("bar.sync %0, %1;" :: "r"(1 + g), "r"(64) : "memory");

            const float2* wf = g_wfrag + (size_t)t * 8 * 8 * 32;
#pragma unroll
            for (int kq = 0; kq < 4; kq++) {
                int k = 4 * hc + kq;   // global k-step (ascending across chunks)
                unsigned a[2][4];
#pragma unroll
                for (int mi = 0; mi < 2; mi++) {
                    const float* base = buf + (32 * g + mi * 16 + gr) * CSTR + 8 * kq + tc;
                    a[mi][0] = __float_as_uint(base[0]);
                    a[mi][1] = __float_as_uint(base[8 * CSTR]);
                    a[mi][2] = __float_as_uint(base[4]);
                    a[mi][3] = __float_as_uint(base[8 * CSTR + 4]);
                }
#pragma unroll
                for (int ni = 0; ni < 4; ni++) {
                    int ni_g = 4 * h + ni;
                    float2 b = __ldg(&wf[(k * 8 + ni_g) * 32 + lane]);
                    unsigned b0 = __float_as_uint(b.x);
                    unsigned b1 = __float_as_uint(b.y);
#pragma unroll
                    for (int mi = 0; mi < 2; mi++) {
                        asm volatile(
                            "mma.sync.aligned.m16n8k8.row.col.f32.tf32.tf32.f32 "
                            "{%0,%1,%2,%3}, {%4,%5,%6,%7}, {%8,%9}, {%0,%1,%2,%3};"
                            : "+f"(acc[mi][ni][0]), "+f"(acc[mi][ni][1]),
                              "+f"(acc[mi][ni][2]), "+f"(acc[mi][ni][3])
                            : "r"(a[mi][0]), "r"(a[mi][1]), "r"(a[mi][2]), "r"(a[mi][3]),
                              "r"(b0), "r"(b1));
                    }
                }
            }
        }
    }

    size_t ob = (size_t)n * CoN * HW + (size_t)y * Ww + x0;
#pragma unroll
    for (int ni = 0; ni < 4; ni++) {
        int o = 8 * (4 * h + ni) + 2 * tc;
#pragma unroll
        for (int mi = 0; mi < 2; mi++) {
            int pr = 32 * g + mi * 16 + gr;
            out[ob + (size_t)o * HW + pr]           = acc[mi][ni][0];
            out[ob + (size_t)(o + 1) * HW + pr]     = acc[mi][ni][1];
            out[ob + (size_t)o * HW + pr + 8]       = acc[mi][ni][2];
            out[ob + (size_t)(o + 1) * HW + pr + 8] = acc[mi][ni][3];
        }
    }
}

// ---------------------------------------------------------------------------
extern "C" void kernel_launch(void* const* d_in, const int* in_sizes, int n_in,
                              void* d_out, int out_size)
{
    const float* x    = (const float*)d_in[0];
    const float* woff = (const float*)d_in[1];
    const float* boff = (const float*)d_in[2];
    const float* wdef = (const float*)d_in[3];
    const float* bdef = (const float*)d_in[4];
    float* out = (float*)d_out;

    wfrag_kernel<<<(9 * 8 * 8 * 32 + 255) / 256, 256>>>(wdef);
    wofrag_kernel<<<(72 * 3 * 32 + 255) / 256, 256>>>(woff);
    pack4_kernel<<<(Nn * 16 * HW) / 256, 256>>>(x);
    offset_mma_kernel<<<dim3(Ww / 128, Hh / 2, Nn), 128>>>(boff);
    deform_mma_kernel<<<dim3(Ww / 64, Hh, Nn), 128>>>(bdef, out);
}

// round 17
// speedup vs baseline: 2.2496x; 2.2496x over previous
#include <cuda_runtime.h>
#include <cuda_bf16.h>

#define Nn  8
#define Cc  64
#define Hh  128
#define Ww  512
#define CoN 64
#define HW  (Hh * Ww)      // 65536
#define NOFF 18
#define CSTR 36            // deform chunk tile stride (floats): 144B, conflict-free
#define XSTR 136           // offset-conv x-tile stride

// Scratch: offsets, channel-quad-packed x, tf32 B-fragment tables.
__device__ float  g_off[(size_t)Nn * NOFF * HW];   // ~36 MB
__device__ float4 g_x4[(size_t)Nn * 16 * HW];      // ~134 MB  [n][c/4][y][x]
__device__ float2 g_wfrag[9 * 8 * 8 * 32];         // deform B frags [t][k][ni][lane]
__device__ float2 g_wofrag[72 * 3 * 32];           // offset B frags

__device__ __forceinline__ unsigned f2tf32(float v) {
    unsigned u;
    asm("cvt.rna.tf32.f32 %0, %1;" : "=r"(u) : "f"(v));
    return u;
}

// ---------------------------------------------------------------------------
// Kernel T: pack x NCHW -> [n][c/4][y][x] float4 (channel-quad interleave).
// ---------------------------------------------------------------------------
__global__ void __launch_bounds__(256) pack4_kernel(const float* __restrict__ x) {
    int idx = blockIdx.x * 256 + threadIdx.x;   // over Nn*16*HW
    int yx   = idx & (HW - 1);
    int rest = idx >> 16;
    int cq   = rest & 15;
    int n    = rest >> 4;
    const float* src = x + ((size_t)(n * 64 + cq * 4)) * HW + yx;
    g_x4[idx] = make_float4(src[0], src[HW], src[2 * HW], src[3 * HW]);
}

// ---------------------------------------------------------------------------
// Kernel 0a: deform B fragments (m16n8k8 tf32).
// ---------------------------------------------------------------------------
__global__ void wfrag_kernel(const float* __restrict__ wdef) {
    int idx = blockIdx.x * 256 + threadIdx.x;
    if (idx >= 9 * 8 * 8 * 32) return;
    int lane = idx & 31;
    int ni   = (idx >> 5) & 7;
    int k    = (idx >> 8) & 7;
    int t    = idx >> 11;
    int c = 8 * k + (lane & 3);
    int o = 8 * ni + (lane >> 2);
    float b0 = wdef[(o * 64 + c) * 9 + t];
    float b1 = wdef[(o * 64 + c + 4) * 9 + t];
    g_wfrag[idx] = make_float2(__uint_as_float(f2tf32(b0)),
                               __uint_as_float(f2tf32(b1)));
}

// ---------------------------------------------------------------------------
// Kernel 0b: offset-conv B fragments (oc padded 18 -> 24).
// ---------------------------------------------------------------------------
__global__ void wofrag_kernel(const float* __restrict__ woff) {
    int idx = blockIdx.x * 256 + threadIdx.x;
    if (idx >= 72 * 3 * 32) return;
    int lane = idx & 31;
    int rem  = idx >> 5;
    int ni   = rem % 3;
    int ks   = rem / 3;
    int gr = lane >> 2, tc = lane & 3;
    int k0 = 8 * ks + tc;
    int oc = 8 * ni + gr;
    float b0 = (oc < 18) ? woff[oc * 576 + k0]     : 0.0f;
    float b1 = (oc < 18) ? woff[oc * 576 + k0 + 4] : 0.0f;
    g_wofrag[(ks * 3 + ni) * 32 + lane] =
        make_float2(__uint_as_float(f2tf32(b0)), __uint_as_float(f2tf32(b1)));
}

// ---------------------------------------------------------------------------
// Kernel 1: offset conv via tf32 MMA, row-pair + quad fill (Round 15 verbatim).
// ---------------------------------------------------------------------------
__global__ void __launch_bounds__(128) offset_mma_kernel(
    const float* __restrict__ boff)
{
    __shared__ float sx[32 * XSTR];   // 17408 B

    int tid  = threadIdx.x;
    int lane = tid & 31;
    int warp = tid >> 5;
    int gr   = lane >> 2;
    int tc   = lane & 3;
    int rowsel = warp >> 1;
    int pxb    = 64 * (warp & 1);

    int x0 = blockIdx.x * 128;
    int y0 = blockIdx.y * 2;
    int n  = blockIdx.z;

    float acc[4][3][4];
#pragma unroll
    for (int ni = 0; ni < 3; ni++) {
        int oc = 8 * ni + 2 * tc;
        float blo = (oc < 18)     ? __ldg(&boff[oc])     : 0.0f;
        float bhi = (oc + 1 < 18) ? __ldg(&boff[oc + 1]) : 0.0f;
#pragma unroll
        for (int mi = 0; mi < 4; mi++) {
            acc[mi][ni][0] = blo; acc[mi][ni][1] = bhi;
            acc[mi][ni][2] = blo; acc[mi][ni][3] = bhi;
        }
    }

    const float4* xq = g_x4 + (size_t)n * 16 * HW;

    for (int ch = 0; ch < 8; ch++) {
        __syncthreads();
        for (int idx = tid; idx < 1040; idx += 128) {
            int row8 = idx / 130;
            int col  = idx - 130 * row8;
            int qi   = row8 >> 2;
            int i    = row8 & 3;
            int yy = y0 + i - 1;
            int xx = x0 + col - 1;
            float4 v = make_float4(0.f, 0.f, 0.f, 0.f);
            if (yy >= 0 && yy < Hh && xx >= 0 && xx < Ww)
                v = xq[(size_t)(ch * 2 + qi) * HW + yy * Ww + xx];
            int rbase = ((qi << 2) << 2) + i;
            sx[(rbase)      * XSTR + col] = __uint_as_float(f2tf32(v.x));
            sx[(rbase + 4)  * XSTR + col] = __uint_as_float(f2tf32(v.y));
            sx[(rbase + 8)  * XSTR + col] = __uint_as_float(f2tf32(v.z));
            sx[(rbase + 12) * XSTR + col] = __uint_as_float(f2tf32(v.w));
        }
        __syncthreads();

#pragma unroll
        for (int kk = 0; kk < 9; kk++) {
            int kl = 8 * kk + tc;
            int c0 = kl / 9,  t0 = kl - 9 * c0;
            int i0 = t0 / 3,  j0 = t0 - 3 * i0;
            int kl2 = kl + 4;
            int c1 = kl2 / 9, t1 = kl2 - 9 * c1;
            int i1 = t1 / 3,  j1 = t1 - 3 * i1;
            int off0 = ((c0 << 2) + i0 + rowsel) * XSTR + j0 + pxb;
            int off1 = ((c1 << 2) + i1 + rowsel) * XSTR + j1 + pxb;

            const float2* wf = g_wofrag + (size_t)(ch * 9 + kk) * 96;
            float2 bfr[3];
#pragma unroll
            for (int ni = 0; ni < 3; ni++) bfr[ni] = __ldg(&wf[ni * 32 + lane]);

#pragma unroll
            for (int mi = 0; mi < 4; mi++) {
                int m = mi * 16 + gr;
                unsigned a0 = __float_as_uint(sx[off0 + m]);
                unsigned a1 = __float_as_uint(sx[off0 + m + 8]);
                unsigned a2 = __float_as_uint(sx[off1 + m]);
                unsigned a3 = __float_as_uint(sx[off1 + m + 8]);
#pragma unroll
                for (int ni = 0; ni < 3; ni++) {
                    unsigned b0 = __float_as_uint(bfr[ni].x);
                    unsigned b1 = __float_as_uint(bfr[ni].y);
                    asm volatile(
                        "mma.sync.aligned.m16n8k8.row.col.f32.tf32.tf32.f32 "
                        "{%0,%1,%2,%3}, {%4,%5,%6,%7}, {%8,%9}, {%0,%1,%2,%3};"
                        : "+f"(acc[mi][ni][0]), "+f"(acc[mi][ni][1]),
                          "+f"(acc[mi][ni][2]), "+f"(acc[mi][ni][3])
                        : "r"(a0), "r"(a1), "r"(a2), "r"(a3),
                          "r"(b0), "r"(b1));
                }
            }
        }
    }

    size_t ob = (size_t)n * NOFF * HW + (size_t)(y0 + rowsel) * Ww + x0 + pxb;
#pragma unroll
    for (int ni = 0; ni < 3; ni++) {
        int oc = 8 * ni + 2 * tc;
#pragma unroll
        for (int mi = 0; mi < 4; mi++) {
            int pr = mi * 16 + gr;
            if (oc < 18) {
                g_off[ob + (size_t)oc * HW + pr]     = acc[mi][ni][0];
                g_off[ob + (size_t)oc * HW + pr + 8] = acc[mi][ni][2];
            }
            if (oc + 1 < 18) {
                g_off[ob + (size_t)(oc + 1) * HW + pr]     = acc[mi][ni][1];
                g_off[ob + (size_t)(oc + 1) * HW + pr + 8] = acc[mi][ni][3];
            }
        }
    }
}

// ---------------------------------------------------------------------------
// Kernel 2: deformable conv — K-chunked (2x32ch) double buffer, 18.4 KB smem.
// __launch_bounds__(128, 7): reg cap 73 -> 7 CTAs/SM (28 warps, +17%).
// k order ascending across chunks -> output bit-identical to Round 14/15.
// ---------------------------------------------------------------------------
__global__ void __launch_bounds__(128, 7) deform_mma_kernel(
    const float* __restrict__ bdef,
    float* __restrict__ out)
{
    __shared__ __align__(16) float sS[2][64 * CSTR];   // 2 x 9216 B

    int tid  = threadIdx.x;
    int lane = tid & 31;
    int warp = tid >> 5;
    int g    = warp & 1;      // pixel group
    int h    = warp >> 1;     // och quarter / gather 16-ch half of chunk
    int gr   = lane >> 2;
    int tc   = lane & 3;

    int x0  = blockIdx.x * 64;
    int y   = blockIdx.y;
    int n   = blockIdx.z;
    int pxl = tid & 63;
    int xg  = x0 + pxl;

    float acc[2][4][4];
#pragma unroll
    for (int ni = 0; ni < 4; ni++) {
        int ni_g = 4 * h + ni;
        float blo = __ldg(&bdef[8 * ni_g + 2 * tc]);
        float bhi = __ldg(&bdef[8 * ni_g + 2 * tc + 1]);
#pragma unroll
        for (int mi = 0; mi < 2; mi++) {
            acc[mi][ni][0] = blo; acc[mi][ni][1] = bhi;
            acc[mi][ni][2] = blo; acc[mi][ni][3] = bhi;
        }
    }

    const float4* xqb = g_x4 + (size_t)n * 16 * HW;
    const float* offb = g_off + (size_t)n * NOFF * HW + (size_t)y * Ww + xg;

    float dy = offb[0];
    float dx = offb[(size_t)HW];

    int bufsel = 0;

    for (int t = 0; t < 9; t++) {
        int i = t / 3, j = t % 3;
        float py  = (float)(y + i - 1) + dy;
        float pxf = (float)(xg + j - 1) + dx;

        if (t < 8) {
            dy = offb[(size_t)(2 * t + 2) * HW];
            dx = offb[(size_t)(2 * t + 3) * HW];
        }

        float fy = floorf(py), fx = floorf(pxf);
        float wy1 = py - fy, wx1 = pxf - fx;
        float wy0 = 1.0f - wy1, wx0 = 1.0f - wx1;
        int iy0 = (int)fy, ix0 = (int)fx;
        int iy1 = iy0 + 1, ix1 = ix0 + 1;

        float gy0 = (iy0 >= 0 && iy0 < Hh) ? wy0 : 0.0f;
        float gy1 = (iy1 >= 0 && iy1 < Hh) ? wy1 : 0.0f;
        float gx0 = (ix0 >= 0 && ix0 < Ww) ? wx0 : 0.0f;
        float gx1 = (ix1 >= 0 && ix1 < Ww) ? wx1 : 0.0f;
        float c00 = gy0 * gx0, c01 = gy0 * gx1;
        float c10 = gy1 * gx0, c11 = gy1 * gx1;

        int yc0 = min(max(iy0, 0), Hh - 1), yc1 = min(max(iy1, 0), Hh - 1);
        int xc0 = min(max(ix0, 0), Ww - 1), xc1 = min(max(ix1, 0), Ww - 1);
        int o00 = yc0 * Ww + xc0, o01 = yc0 * Ww + xc1;
        int o10 = yc1 * Ww + xc0, o11 = yc1 * Ww + xc1;

#pragma unroll
        for (int hc = 0; hc < 2; hc++) {
            float* buf = sS[bufsel];
            bufsel ^= 1;

            {   // gather 4 quads (16 ch) of chunk hc, half h, pixel pxl
                float4* srow = (float4*)(buf + pxl * CSTR + 16 * h);
                const float4* p = xqb + (size_t)(hc * 8 + h * 4) * HW;
#pragma unroll
                for (int q = 0; q < 4; q++) {
                    float4 a = p[o00];
                    float4 b = p[o01];
                    float4 c = p[o10];
                    float4 d = p[o11];
                    float4 v;
                    v.x = fmaf(c11, d.x, fmaf(c10, c.x, fmaf(c01, b.x, c00 * a.x)));
                    v.y = fmaf(c11, d.y, fmaf(c10, c.y, fmaf(c01, b.y, c00 * a.y)));
                    v.z = fmaf(c11, d.z, fmaf(c10, c.z, fmaf(c01, b.z, c00 * a.z)));
                    v.w = fmaf(c11, d.w, fmaf(c10, c.w, fmaf(c01, b.w, c00 * a.w)));
                    v.x = __uint_as_float(f2tf32(v.x));
                    v.y = __uint_as_float(f2tf32(v.y));
                    v.z = __uint_as_float(f2tf32(v.z));
                    v.w = __uint_as_float(f2tf32(v.w));
                    srow[q] = v;
                    p += HW;
                }
            }

            asm volatile("bar.sync %0, %1;" :: "r"(1 + g), "r"(64) : "memory");

            const float2* wf = g_wfrag + (size_t)t * 8 * 8 * 32;
#pragma unroll
            for (int kq = 0; kq < 4; kq++) {
                int k = 4 * hc + kq;
                unsigned a[2][4];
#pragma unroll
                for (int mi = 0; mi < 2; mi++) {
                    const float* base = buf + (32 * g + mi * 16 + gr) * CSTR + 8 * kq + tc;
                    a[mi][0] = __float_as_uint(base[0]);
                    a[mi][1] = __float_as_uint(base[8 * CSTR]);
                    a[mi][2] = __float_as_uint(base[4]);
                    a[mi][3] = __float_as_uint(base[8 * CSTR + 4]);
                }
#pragma unroll
                for (int ni = 0; ni < 4; ni++) {
                    int ni_g = 4 * h + ni;
                    float2 b = __ldg(&wf[(k * 8 + ni_g) * 32 + lane]);
                    unsigned b0 = __float_as_uint(b.x);
                    unsigned b1 = __float_as_uint(b.y);
#pragma unroll
                    for (int mi = 0; mi < 2; mi++) {
                        asm volatile(
                            "mma.sync.aligned.m16n8k8.row.col.f32.tf32.tf32.f32 "
                            "{%0,%1,%2,%3}, {%4,%5,%6,%7}, {%8,%9}, {%0,%1,%2,%3};"
                            : "+f"(acc[mi][ni][0]), "+f"(acc[mi][ni][1]),
                              "+f"(acc[mi][ni][2]), "+f"(acc[mi][ni][3])
                            : "r"(a[mi][0]), "r"(a[mi][1]), "r"(a[mi][2]), "r"(a[mi][3]),
                              "r"(b0), "r"(b1));
                    }
                }
            }
        }
    }

    size_t ob = (size_t)n * CoN * HW + (size_t)y * Ww + x0;
#pragma unroll
    for (int ni = 0; ni < 4; ni++) {
        int o = 8 * (4 * h + ni) + 2 * tc;
#pragma unroll
        for (int mi = 0; mi < 2; mi++) {
            int pr = 32 * g + mi * 16 + gr;
            out[ob + (size_t)o * HW + pr]           = acc[mi][ni][0];
            out[ob + (size_t)(o + 1) * HW + pr]     = acc[mi][ni][1];
            out[ob + (size_t)o * HW + pr + 8]       = acc[mi][ni][2];
            out[ob + (size_t)(o + 1) * HW + pr + 8] = acc[mi][ni][3];
        }
    }
}

// ---------------------------------------------------------------------------
extern "C" void kernel_launch(void* const* d_in, const int* in_sizes, int n_in,
                              void* d_out, int out_size)
{
    const float* x    = (const float*)d_in[0];
    const float* woff = (const float*)d_in[1];
    const float* boff = (const float*)d_in[2];
    const float* wdef = (const float*)d_in[3];
    const float* bdef = (const float*)d_in[4];
    float* out = (float*)d_out;

    wfrag_kernel<<<(9 * 8 * 8 * 32 + 255) / 256, 256>>>(wdef);
    wofrag_kernel<<<(72 * 3 * 32 + 255) / 256, 256>>>(woff);
    pack4_kernel<<<(Nn * 16 * HW) / 256, 256>>>(x);
    offset_mma_kernel<<<dim3(Ww / 128, Hh / 2, Nn), 128>>>(boff);
    deform_mma_kernel<<<dim3(Ww / 64, Hh, Nn), 128>>>(bdef, out);
}